// round 14
// baseline (speedup 1.0000x reference)
#include <cuda_runtime.h>
#include <cstdint>

// Problem constants
#define NB    4
#define LL    2048
#define EE    1024
#define HID   1024
#define HEADS 16
#define DH    64
#define MROWS 8192
#define NPAIR 64
#define RBG   4             // row-block groups in score kernel
#define RPG   4             // row-blocks per group (RBG*RPG*128 = 2048)

#define PERSIST_CTAS 296    // 2 CTAs/SM x 148 SMs

// Scratch (static device globals)
__device__ float g_Q[MROWS * HID];
__device__ float g_K[MROWS * HID];
__device__ float g_V[MROWS * HID];
__device__ float g_diagE[NPAIR * LL];
__device__ float g_part[RBG * NPAIR * LL];    // per-rowgroup column partial sums
__device__ float g_diag[NPAIR * LL];          // final diagE / colsum

// ---------------------------------------------------------------------------
__device__ __forceinline__ uint32_t f2tf32(float x) {
    uint32_t r;
    asm("cvt.rna.tf32.f32 %0, %1;" : "=r"(r) : "f"(x));
    return r;
}

__device__ __forceinline__ void mma_tf32(float c[4], const uint32_t a[4], const uint32_t b[2]) {
    asm volatile(
        "mma.sync.aligned.m16n8k8.row.col.f32.tf32.tf32.f32 "
        "{%0,%1,%2,%3}, {%4,%5,%6,%7}, {%8,%9}, {%0,%1,%2,%3};\n"
        : "+f"(c[0]), "+f"(c[1]), "+f"(c[2]), "+f"(c[3])
        : "r"(a[0]), "r"(a[1]), "r"(a[2]), "r"(a[3]), "r"(b[0]), "r"(b[1]));
}

__device__ __forceinline__ float4 tf4(float4 v) {
    float4 w;
    w.x = __uint_as_float(f2tf32(v.x));
    w.y = __uint_as_float(f2tf32(v.y));
    w.z = __uint_as_float(f2tf32(v.z));
    w.w = __uint_as_float(f2tf32(v.w));
    return w;
}

// ---------------------------------------------------------------------------
// Tensor-core GEMM body (R8 layout): C = (scale ? diag*A : A) @ B + bias.
// Block tile 128x128, BK=16, 8 warps (4m x 2n), warp tile 32x64.
// Double-buffered smem, one __syncthreads per k-tile, 2 CTAs/SM.
// ---------------------------------------------------------------------------
#define GBM 128
#define GBN 128
#define GBK 16
#define ASTR 20
#define BSTR 136
#define ASZ (GBM * ASTR)   // 2560 floats
#define BSZ (GBK * BSTR)   // 2176 floats

__device__ __forceinline__ float scale_of(const float* scale, int row, int k) {
    int lr = row & (LL - 1);
    int n  = row >> 11;
    int h  = lr >> 7;
    int a  = ((lr & 127) << 4) | (k >> 6);
    return scale[((size_t)(n * HEADS + h)) * LL + a];
}

__device__ __forceinline__ void gemm_body(
    const float* __restrict__ A, const float* __restrict__ B,
    const float* __restrict__ bias, float* __restrict__ C,
    const float* __restrict__ scale, int N, int K, int bm, int bn,
    float* As, float* Bs)
{
    const int t    = threadIdx.x;
    const int lane = t & 31, wid = t >> 5;
    const int wm = wid & 3, wn = wid >> 2;
    const int r = lane >> 2, cq = lane & 3;

    float acc[2][8][4];
    #pragma unroll
    for (int mt = 0; mt < 2; mt++)
        #pragma unroll
        for (int nt = 0; nt < 8; nt++)
            #pragma unroll
            for (int j = 0; j < 4; j++) acc[mt][nt][j] = 0.f;

    int arow[2], aq[2], brow[2], bq[2];
    #pragma unroll
    for (int i = 0; i < 2; i++) {
        int idx = t + i * 256;
        arow[i] = idx >> 2;  aq[i] = idx & 3;      // A: row 0..127, kq 0..3
        brow[i] = idx >> 5;  bq[i] = idx & 31;     // B: k 0..15, nq 0..31
    }

    float4 pa[2], pb[2];

    // Stage k-tile 0 into buffer 0
    #pragma unroll
    for (int i = 0; i < 2; i++) {
        pa[i] = *reinterpret_cast<const float4*>(&A[(size_t)(bm + arow[i]) * K + aq[i] * 4]);
        pb[i] = *reinterpret_cast<const float4*>(&B[(size_t)brow[i] * N + bn + bq[i] * 4]);
    }
    #pragma unroll
    for (int i = 0; i < 2; i++) {
        float4 v = pa[i];
        if (scale) {
            float dd = scale_of(scale, bm + arow[i], aq[i] * 4);
            v.x *= dd; v.y *= dd; v.z *= dd; v.w *= dd;
        }
        *reinterpret_cast<float4*>(&As[arow[i] * ASTR + aq[i] * 4]) = tf4(v);
        *reinterpret_cast<float4*>(&Bs[brow[i] * BSTR + bq[i] * 4]) = tf4(pb[i]);
    }
    __syncthreads();

    const int KT = K / GBK;
    for (int kt = 0; kt < KT; kt++) {
        const int b = kt & 1;
        const float* Asb = &As[b * ASZ];
        const float* Bsb = &Bs[b * BSZ];
        const int k0n = (kt + 1) * GBK;

        if (kt + 1 < KT) {
            #pragma unroll
            for (int i = 0; i < 2; i++) {
                pa[i] = *reinterpret_cast<const float4*>(&A[(size_t)(bm + arow[i]) * K + k0n + aq[i] * 4]);
                pb[i] = *reinterpret_cast<const float4*>(&B[(size_t)(k0n + brow[i]) * N + bn + bq[i] * 4]);
            }
        }

        #pragma unroll
        for (int kk = 0; kk < 2; kk++) {
            const int kb = kk * 8;
            uint32_t af[2][4], bf[8][2];
            #pragma unroll
            for (int mt = 0; mt < 2; mt++) {
                int rb = wm * 32 + mt * 16;
                af[mt][0] = __float_as_uint(Asb[(rb + r) * ASTR + kb + cq]);
                af[mt][1] = __float_as_uint(Asb[(rb + 8 + r) * ASTR + kb + cq]);
                af[mt][2] = __float_as_uint(Asb[(rb + r) * ASTR + kb + 4 + cq]);
                af[mt][3] = __float_as_uint(Asb[(rb + 8 + r) * ASTR + kb + 4 + cq]);
            }
            #pragma unroll
            for (int nt = 0; nt < 8; nt++) {
                int cb = wn * 64 + nt * 8 + r;
                bf[nt][0] = __float_as_uint(Bsb[(kb + cq) * BSTR + cb]);
                bf[nt][1] = __float_as_uint(Bsb[(kb + 4 + cq) * BSTR + cb]);
            }
            #pragma unroll
            for (int mt = 0; mt < 2; mt++)
                #pragma unroll
                for (int nt = 0; nt < 8; nt++)
                    mma_tf32(acc[mt][nt], af[mt], bf[nt]);
        }

        if (kt + 1 < KT) {
            float* Asn = &As[(1 - b) * ASZ];
            float* Bsn = &Bs[(1 - b) * BSZ];
            #pragma unroll
            for (int i = 0; i < 2; i++) {
                float4 v = pa[i];
                if (scale) {
                    float dd = scale_of(scale, bm + arow[i], k0n + aq[i] * 4);
                    v.x *= dd; v.y *= dd; v.z *= dd; v.w *= dd;
                }
                *reinterpret_cast<float4*>(&Asn[arow[i] * ASTR + aq[i] * 4]) = tf4(v);
                *reinterpret_cast<float4*>(&Bsn[brow[i] * BSTR + bq[i] * 4]) = tf4(pb[i]);
            }
        }
        __syncthreads();
    }

    // Epilogue with bias (registers + global only; smem safe for next tile)
    #pragma unroll
    for (int mt = 0; mt < 2; mt++) {
        int row0 = bm + wm * 32 + mt * 16 + r;
        #pragma unroll
        for (int nt = 0; nt < 8; nt++) {
            int col = bn + wn * 64 + nt * 8 + cq * 2;
            float b0 = bias[col], b1 = bias[col + 1];
            float2 v0 = make_float2(acc[mt][nt][0] + b0, acc[mt][nt][1] + b1);
            float2 v1 = make_float2(acc[mt][nt][2] + b0, acc[mt][nt][3] + b1);
            *reinterpret_cast<float2*>(&C[(size_t)row0 * N + col]) = v0;
            *reinterpret_cast<float2*>(&C[(size_t)(row0 + 8) * N + col]) = v1;
        }
    }
}

// Persistent fused Q/K/V projection: 1536 tiles over PERSIST_CTAS blocks.
__global__ __launch_bounds__(256, 2) void gemm_qkv(
    const float* __restrict__ X,
    const float* __restrict__ Wq, const float* __restrict__ Wk, const float* __restrict__ Wv,
    const float* __restrict__ bq, const float* __restrict__ bk, const float* __restrict__ bv,
    float* __restrict__ Q, float* __restrict__ K, float* __restrict__ V)
{
    __shared__ float As[2 * ASZ];
    __shared__ float Bs[2 * BSZ];

    const int NT = (HID / GBN) * (MROWS / GBM) * 3;   // 1536
    for (int tile = blockIdx.x; tile < NT; tile += gridDim.x) {
        int z   = tile >> 9;          // / 512
        int rem = tile & 511;
        int by  = rem >> 3;           // 0..63
        int bx  = rem & 7;            // 0..7
        const float* B    = (z == 0) ? Wq : (z == 1) ? Wk : Wv;
        const float* bias = (z == 0) ? bq : (z == 1) ? bk : bv;
        float*       C    = (z == 0) ? Q  : (z == 1) ? K  : V;
        gemm_body(X, B, bias, C, nullptr, HID, EE, by * GBM, bx * GBN, As, Bs);
    }
}

// Persistent O projection with fused diag scaling of A (=V). 512 tiles.
__global__ __launch_bounds__(256, 2) void gemm_o(
    const float* __restrict__ V, const float* __restrict__ Wo,
    const float* __restrict__ bo, float* __restrict__ C,
    const float* __restrict__ diag)
{
    __shared__ float As[2 * ASZ];
    __shared__ float Bs[2 * BSZ];

    const int NT = (HID / GBN) * (MROWS / GBM);       // 512
    for (int tile = blockIdx.x; tile < NT; tile += gridDim.x) {
        int by = tile >> 3;
        int bx = tile & 7;
        gemm_body(V, Wo, bo, C, diag, HID, HID, by * GBM, bx * GBN, As, Bs);
    }
}

// ---------------------------------------------------------------------------
// Score kernel with K-tile residency. Block (cb, rbg, p):
//   K[cb] tile stays in smem; loop over 4 Q row-blocks rb = rbg*4 + it:
//   S = Q[rb] @ K[cb]^T (128x128x64 tf32 mma), e = exp(S/1024),
//   column partial sums accumulated in REGISTERS across the 4 row-blocks,
//   diag captured when rb==cb. One smem reduce + one partG write per block.
// 8 warps (4a x 2b), warp tile 32(a) x 64(b). R8 fragment layout (SSTR 68).
// ---------------------------------------------------------------------------
#define SSTR 68

__global__ __launch_bounds__(256, 2) void score_diag_tc(
    const float* __restrict__ Q, const float* __restrict__ Km,
    float* __restrict__ diagE, float* __restrict__ partG)
{
    extern __shared__ float sm[];
    float* Ks   = sm;                   // 128 x SSTR
    float* Qs   = sm + 128 * SSTR;      // 128 x SSTR
    float* csum = sm + 2 * 128 * SSTR;  // 128

    const int t    = threadIdx.x;
    const int lane = t & 31, wid = t >> 5;
    const int wm = wid & 3, wn = wid >> 2;
    const int r = lane >> 2, cq = lane & 3;

    const int cb  = blockIdx.x;         // column block 0..15
    const int rbg = blockIdx.y;         // row-block group 0..3
    const int p   = blockIdx.z;         // pair 0..63
    const int bn  = cb * 128;
    const float* Qh = Q  + (size_t)p * LL * DH;
    const float* Kh = Km + (size_t)p * LL * DH;

    // Load K tile (cols) once, tf32-rounded
    #pragma unroll
    for (int i = 0; i < 8; i++) {
        int idx = t + i * 256;
        int row = idx >> 4, q = idx & 15;
        float4 v = *reinterpret_cast<const float4*>(&Kh[(size_t)(bn + row) * DH + q * 4]);
        *reinterpret_cast<float4*>(&Ks[row * SSTR + q * 4]) = tf4(v);
    }

    const float S = 1.0f / 1024.0f;
    float partial[8][2];
    #pragma unroll
    for (int nt = 0; nt < 8; nt++) { partial[nt][0] = 0.f; partial[nt][1] = 0.f; }

    for (int it = 0; it < RPG; it++) {
        const int rb = rbg * RPG + it;
        const int a0 = rb * 128;

        if (it > 0) __syncthreads();    // previous Qs consumers done
        #pragma unroll
        for (int i = 0; i < 8; i++) {
            int idx = t + i * 256;
            int row = idx >> 4, q = idx & 15;
            float4 v = *reinterpret_cast<const float4*>(&Qh[(size_t)(a0 + row) * DH + q * 4]);
            *reinterpret_cast<float4*>(&Qs[row * SSTR + q * 4]) = tf4(v);
        }
        __syncthreads();

        float acc[2][8][4];
        #pragma unroll
        for (int mt = 0; mt < 2; mt++)
            #pragma unroll
            for (int nt = 0; nt < 8; nt++)
                #pragma unroll
                for (int j = 0; j < 4; j++) acc[mt][nt][j] = 0.f;

        #pragma unroll
        for (int kk = 0; kk < 8; kk++) {
            const int kb = kk * 8;
            uint32_t af[2][4], bf[8][2];
            #pragma unroll
            for (int mt = 0; mt < 2; mt++) {
                int rbm = wm * 32 + mt * 16;
                af[mt][0] = __float_as_uint(Qs[(rbm + r) * SSTR + kb + cq]);
                af[mt][1] = __float_as_uint(Qs[(rbm + 8 + r) * SSTR + kb + cq]);
                af[mt][2] = __float_as_uint(Qs[(rbm + r) * SSTR + kb + 4 + cq]);
                af[mt][3] = __float_as_uint(Qs[(rbm + 8 + r) * SSTR + kb + 4 + cq]);
            }
            #pragma unroll
            for (int nt = 0; nt < 8; nt++) {
                int cbi = wn * 64 + nt * 8 + r;
                bf[nt][0] = __float_as_uint(Ks[cbi * SSTR + kb + cq]);
                bf[nt][1] = __float_as_uint(Ks[cbi * SSTR + kb + 4 + cq]);
            }
            #pragma unroll
            for (int mt = 0; mt < 2; mt++)
                #pragma unroll
                for (int nt = 0; nt < 8; nt++)
                    mma_tf32(acc[mt][nt], af[mt], bf[nt]);
        }

        // exp + per-warp column partials; capture diagonal when rb==cb
        const bool diagblk = (rb == cb);
        #pragma unroll
        for (int mt = 0; mt < 2; mt++) {
            int arow0 = wm * 32 + mt * 16 + r;
            #pragma unroll
            for (int nt = 0; nt < 8; nt++) {
                #pragma unroll
                for (int j = 0; j < 2; j++) {
                    int bcol = wn * 64 + nt * 8 + cq * 2 + j;
                    float e0 = __expf(acc[mt][nt][j] * S);
                    float e1 = __expf(acc[mt][nt][2 + j] * S);
                    partial[nt][j] += e0 + e1;
                    if (diagblk) {
                        if (arow0 == bcol)     diagE[(size_t)p * LL + bn + bcol] = e0;
                        if (arow0 + 8 == bcol) diagE[(size_t)p * LL + bn + bcol] = e1;
                    }
                }
            }
        }
    }

    // Reduce partials over the 8 row-groups within the warp
    #pragma unroll
    for (int nt = 0; nt < 8; nt++)
        #pragma unroll
        for (int j = 0; j < 2; j++) {
            float v = partial[nt][j];
            v += __shfl_xor_sync(0xFFFFFFFF, v, 4);
            v += __shfl_xor_sync(0xFFFFFFFF, v, 8);
            v += __shfl_xor_sync(0xFFFFFFFF, v, 16);
            partial[nt][j] = v;
        }

    __syncthreads();                    // Qs consumers done; csum safe to init
    if (t < 128) csum[t] = 0.f;
    __syncthreads();
    if (r == 0) {
        #pragma unroll
        for (int nt = 0; nt < 8; nt++)
            #pragma unroll
            for (int j = 0; j < 2; j++)
                atomicAdd(&csum[wn * 64 + nt * 8 + cq * 2 + j], partial[nt][j]);
    }
    __syncthreads();
    if (t < 128)
        partG[((size_t)rbg * NPAIR + p) * LL + bn + t] = csum[t];
}

// ---------------------------------------------------------------------------
// diag[p][c] = diagE[p][c] / sum_rbg part[rbg][p][c]
// ---------------------------------------------------------------------------
__global__ __launch_bounds__(256) void divide_kernel(
    const float* __restrict__ diagE, const float* __restrict__ part,
    float* __restrict__ diag)
{
    int i = blockIdx.x * 256 + threadIdx.x;           // over NPAIR*LL
    if (i >= NPAIR * LL) return;
    float s = 0.f;
    #pragma unroll
    for (int rb = 0; rb < RBG; rb++)
        s += part[(size_t)rb * NPAIR * LL + i];
    diag[i] = diagE[i] / s;
}

// ---------------------------------------------------------------------------
extern "C" void kernel_launch(void* const* d_in, const int* in_sizes, int n_in,
                              void* d_out, int out_size)
{
    const float* X  = (const float*)d_in[0];
    const float* Wq = (const float*)d_in[1];
    const float* bq = (const float*)d_in[2];
    const float* Wk = (const float*)d_in[3];
    const float* bk = (const float*)d_in[4];
    const float* Wv = (const float*)d_in[5];
    const float* bv = (const float*)d_in[6];
    const float* Wo = (const float*)d_in[7];
    const float* bo = (const float*)d_in[8];
    float* out = (float*)d_out;

    float *Q, *K, *V, *dgE, *pt, *dg;
    cudaGetSymbolAddress((void**)&Q,   g_Q);
    cudaGetSymbolAddress((void**)&K,   g_K);
    cudaGetSymbolAddress((void**)&V,   g_V);
    cudaGetSymbolAddress((void**)&dgE, g_diagE);
    cudaGetSymbolAddress((void**)&pt,  g_part);
    cudaGetSymbolAddress((void**)&dg,  g_diag);

    const int score_smem = (2 * 128 * SSTR + 128) * sizeof(float);
    static int attr_done = 0;
    if (!attr_done) {
        cudaFuncSetAttribute(score_diag_tc,
                             cudaFuncAttributeMaxDynamicSharedMemorySize, score_smem);
        attr_done = 1;
    }

    gemm_qkv<<<PERSIST_CTAS, 256>>>(X, Wq, Wk, Wv, bq, bk, bv, Q, K, V);

    dim3 sgrid(LL / 128, RBG, NPAIR);           // (16, 4, 64) = 4096 blocks
    score_diag_tc<<<sgrid, 256, score_smem>>>(Q, K, dgE, pt);

    divide_kernel<<<(NPAIR * LL + 255) / 256, 256>>>(dgE, pt, dg);

    gemm_o<<<PERSIST_CTAS, 256>>>(V, Wo, bo, out, dg);
}

// round 15
// speedup vs baseline: 1.1457x; 1.1457x over previous
#include <cuda_runtime.h>
#include <cstdint>

// Problem constants
#define NB    4
#define LL    2048
#define EE    1024
#define HID   1024
#define HEADS 16
#define DH    64
#define MROWS 8192
#define NPAIR 64
#define RBG   4
#define RPG   4

// Scratch (static device globals)
__device__ float g_Q[MROWS * HID];
__device__ float g_K[MROWS * HID];
__device__ float g_V[MROWS * HID];
__device__ float g_Xr[MROWS * EE];      // tf32-rounded X
__device__ float g_Wqr[EE * HID];
__device__ float g_Wkr[EE * HID];
__device__ float g_Wvr[EE * HID];
__device__ float g_Wor[HID * HID];
__device__ float g_diagE[NPAIR * LL];
__device__ float g_part[RBG * NPAIR * LL];
__device__ float g_diag[NPAIR * LL];

// ---------------------------------------------------------------------------
__device__ __forceinline__ uint32_t f2tf32(float x) {
    uint32_t r;
    asm("cvt.rna.tf32.f32 %0, %1;" : "=r"(r) : "f"(x));
    return r;
}

__device__ __forceinline__ float rtf(float x) {
    return __uint_as_float(f2tf32(x));
}

__device__ __forceinline__ void mma_tf32(float c[4], const uint32_t a[4], const uint32_t b[2]) {
    asm volatile(
        "mma.sync.aligned.m16n8k8.row.col.f32.tf32.tf32.f32 "
        "{%0,%1,%2,%3}, {%4,%5,%6,%7}, {%8,%9}, {%0,%1,%2,%3};\n"
        : "+f"(c[0]), "+f"(c[1]), "+f"(c[2]), "+f"(c[3])
        : "r"(a[0]), "r"(a[1]), "r"(a[2]), "r"(a[3]), "r"(b[0]), "r"(b[1]));
}

__device__ __forceinline__ float4 tf4(float4 v) {
    float4 w;
    w.x = rtf(v.x); w.y = rtf(v.y); w.z = rtf(v.z); w.w = rtf(v.w);
    return w;
}

__device__ __forceinline__ uint32_t smem_u32(const void* p) {
    return (uint32_t)__cvta_generic_to_shared(p);
}

#define CP16(dst_u32, src_ptr) \
    asm volatile("cp.async.cg.shared.global [%0], [%1], 16;\n" \
                 :: "r"(dst_u32), "l"(src_ptr) : "memory")
#define CP_COMMIT()  asm volatile("cp.async.commit_group;\n" ::: "memory")
#define CP_WAIT(n)   asm volatile("cp.async.wait_group %0;\n" :: "n"(n) : "memory")

// ---------------------------------------------------------------------------
// Pre-round: dst = tf32_round(src), vectorized by 4.
// ---------------------------------------------------------------------------
__global__ __launch_bounds__(256) void round_copy(
    const float* __restrict__ src, float* __restrict__ dst, int n4)
{
    int i = blockIdx.x * 256 + threadIdx.x;
    if (i >= n4) return;
    reinterpret_cast<float4*>(dst)[i] =
        tf4(reinterpret_cast<const float4*>(src)[i]);
}

// ---------------------------------------------------------------------------
// cp.async GEMM: C = A @ B + bias, A/B already tf32-rounded fp32 in gmem.
// Block 128x128, BK=32, 8 warps (4m x 2n), warp tile 32x64.
// 3-stage cp.async ring, ONE __syncthreads per k-tile.
// A smem [m][k] stride 36; B smem [k][n] stride 136.
// ---------------------------------------------------------------------------
#define GBM 128
#define GBN 128
#define GBK 32
#define ASTR 36
#define BSTR 136
#define ASZ (GBM * ASTR)        // 4608 floats
#define BSZ (GBK * BSTR)        // 4352 floats
#define STG_F (ASZ + BSZ)       // 8960 floats per stage
#define GEMM_SMEM (3 * STG_F * (int)sizeof(float))   // 107520 B

__device__ __forceinline__ void stage_cp(
    const float* __restrict__ A, const float* __restrict__ B,
    int N, int K, int bm, int bn, int k0, float* As, float* Bs, int t)
{
    #pragma unroll
    for (int i = 0; i < 4; i++) {
        int idx = t + i * 256;
        int row = idx >> 3, kq = idx & 7;
        CP16(smem_u32(&As[row * ASTR + kq * 4]),
             &A[(size_t)(bm + row) * K + k0 + kq * 4]);
    }
    #pragma unroll
    for (int i = 0; i < 4; i++) {
        int idx = t + i * 256;
        int kr = idx >> 5, nq = idx & 31;
        CP16(smem_u32(&Bs[kr * BSTR + nq * 4]),
             &B[(size_t)(k0 + kr) * N + bn + nq * 4]);
    }
    CP_COMMIT();
}

__device__ __forceinline__ void gemm_body_cp(
    const float* __restrict__ A, const float* __restrict__ B,
    const float* __restrict__ bias, float* __restrict__ C,
    int N, int K, int bm, int bn, float* sm, bool round_out)
{
    const int t    = threadIdx.x;
    const int lane = t & 31, wid = t >> 5;
    const int wm = wid & 3, wn = wid >> 2;
    const int r = lane >> 2, cq = lane & 3;

    float acc[2][8][4];
    #pragma unroll
    for (int mt = 0; mt < 2; mt++)
        #pragma unroll
        for (int nt = 0; nt < 8; nt++)
            #pragma unroll
            for (int j = 0; j < 4; j++) acc[mt][nt][j] = 0.f;

    const int KT = K / GBK;     // 32

    stage_cp(A, B, N, K, bm, bn, 0, sm, sm + ASZ, t);
    stage_cp(A, B, N, K, bm, bn, GBK, sm + STG_F, sm + STG_F + ASZ, t);

    for (int kt = 0; kt < KT; kt++) {
        if (kt < KT - 2) { CP_WAIT(1); } else { CP_WAIT(0); }
        __syncthreads();

        if (kt + 2 < KT) {
            int s = (kt + 2) % 3;
            stage_cp(A, B, N, K, bm, bn, (kt + 2) * GBK,
                     sm + s * STG_F, sm + s * STG_F + ASZ, t);
        }

        const int cs = kt % 3;
        const float* Asb = sm + cs * STG_F;
        const float* Bsb = sm + cs * STG_F + ASZ;

        #pragma unroll
        for (int kk = 0; kk < 4; kk++) {
            const int kb = kk * 8;
            uint32_t af[2][4], bf[8][2];
            #pragma unroll
            for (int mt = 0; mt < 2; mt++) {
                int rb = wm * 32 + mt * 16;
                af[mt][0] = __float_as_uint(Asb[(rb + r) * ASTR + kb + cq]);
                af[mt][1] = __float_as_uint(Asb[(rb + 8 + r) * ASTR + kb + cq]);
                af[mt][2] = __float_as_uint(Asb[(rb + r) * ASTR + kb + 4 + cq]);
                af[mt][3] = __float_as_uint(Asb[(rb + 8 + r) * ASTR + kb + 4 + cq]);
            }
            #pragma unroll
            for (int nt = 0; nt < 8; nt++) {
                int cb = wn * 64 + nt * 8 + r;
                bf[nt][0] = __float_as_uint(Bsb[(kb + cq) * BSTR + cb]);
                bf[nt][1] = __float_as_uint(Bsb[(kb + 4 + cq) * BSTR + cb]);
            }
            #pragma unroll
            for (int mt = 0; mt < 2; mt++)
                #pragma unroll
                for (int nt = 0; nt < 8; nt++)
                    mma_tf32(acc[mt][nt], af[mt], bf[nt]);
        }
    }

    // Epilogue with bias; optionally tf32-round the stored values
    #pragma unroll
    for (int mt = 0; mt < 2; mt++) {
        int row0 = bm + wm * 32 + mt * 16 + r;
        #pragma unroll
        for (int nt = 0; nt < 8; nt++) {
            int col = bn + wn * 64 + nt * 8 + cq * 2;
            float b0 = bias[col], b1 = bias[col + 1];
            float2 v0 = make_float2(acc[mt][nt][0] + b0, acc[mt][nt][1] + b1);
            float2 v1 = make_float2(acc[mt][nt][2] + b0, acc[mt][nt][3] + b1);
            if (round_out) {
                v0.x = rtf(v0.x); v0.y = rtf(v0.y);
                v1.x = rtf(v1.x); v1.y = rtf(v1.y);
            }
            *reinterpret_cast<float2*>(&C[(size_t)row0 * N + col]) = v0;
            *reinterpret_cast<float2*>(&C[(size_t)(row0 + 8) * N + col]) = v1;
        }
    }
}

// Fused Q/K/V projection on pre-rounded X/W; outputs tf32-rounded.
__global__ __launch_bounds__(256, 2) void gemm_qkv(
    const float* __restrict__ X,
    const float* __restrict__ Wq, const float* __restrict__ Wk, const float* __restrict__ Wv,
    const float* __restrict__ bq, const float* __restrict__ bk, const float* __restrict__ bv,
    float* __restrict__ Q, float* __restrict__ K, float* __restrict__ V)
{
    extern __shared__ float sm[];
    const int z = blockIdx.z;
    const float* B    = (z == 0) ? Wq : (z == 1) ? Wk : Wv;
    const float* bias = (z == 0) ? bq : (z == 1) ? bk : bv;
    float*       C    = (z == 0) ? Q  : (z == 1) ? K  : V;
    gemm_body_cp(X, B, bias, C, HID, EE,
                 blockIdx.y * GBM, blockIdx.x * GBN, sm, true);
}

// O projection on diag-scaled V and pre-rounded Wo; fp32 output.
__global__ __launch_bounds__(256, 2) void gemm_o(
    const float* __restrict__ V, const float* __restrict__ Wo,
    const float* __restrict__ bo, float* __restrict__ C)
{
    extern __shared__ float sm[];
    gemm_body_cp(V, Wo, bo, C, HID, HID,
                 blockIdx.y * GBM, blockIdx.x * GBN, sm, false);
}

// ---------------------------------------------------------------------------
// Score kernel (R12 structure): inputs pre-rounded, so staging is plain copy.
// ---------------------------------------------------------------------------
#define SSTR 68

__global__ __launch_bounds__(256, 2) void score_diag_tc(
    const float* __restrict__ Q, const float* __restrict__ Km,
    float* __restrict__ diagE, float* __restrict__ partG)
{
    extern __shared__ float sm[];
    float* Ks   = sm;                   // 128 x SSTR
    float* Qs   = sm + 128 * SSTR;      // 128 x SSTR
    float* csum = sm + 2 * 128 * SSTR;  // 128

    const int t    = threadIdx.x;
    const int lane = t & 31, wid = t >> 5;
    const int wm = wid & 3, wn = wid >> 2;
    const int r = lane >> 2, cq = lane & 3;

    const int cb  = blockIdx.x;
    const int rbg = blockIdx.y;
    const int p   = blockIdx.z;
    const int bn  = cb * 128;
    const float* Qh = Q  + (size_t)p * LL * DH;
    const float* Kh = Km + (size_t)p * LL * DH;

    #pragma unroll
    for (int i = 0; i < 8; i++) {
        int idx = t + i * 256;
        int row = idx >> 4, q = idx & 15;
        *reinterpret_cast<float4*>(&Ks[row * SSTR + q * 4]) =
            *reinterpret_cast<const float4*>(&Kh[(size_t)(bn + row) * DH + q * 4]);
    }

    const float S = 1.0f / 1024.0f;
    float partial[8][2];
    #pragma unroll
    for (int nt = 0; nt < 8; nt++) { partial[nt][0] = 0.f; partial[nt][1] = 0.f; }

    for (int it = 0; it < RPG; it++) {
        const int rb = rbg * RPG + it;
        const int a0 = rb * 128;

        if (it > 0) __syncthreads();
        #pragma unroll
        for (int i = 0; i < 8; i++) {
            int idx = t + i * 256;
            int row = idx >> 4, q = idx & 15;
            *reinterpret_cast<float4*>(&Qs[row * SSTR + q * 4]) =
                *reinterpret_cast<const float4*>(&Qh[(size_t)(a0 + row) * DH + q * 4]);
        }
        __syncthreads();

        float acc[2][8][4];
        #pragma unroll
        for (int mt = 0; mt < 2; mt++)
            #pragma unroll
            for (int nt = 0; nt < 8; nt++)
                #pragma unroll
                for (int j = 0; j < 4; j++) acc[mt][nt][j] = 0.f;

        #pragma unroll
        for (int kk = 0; kk < 8; kk++) {
            const int kb = kk * 8;
            uint32_t af[2][4], bf[8][2];
            #pragma unroll
            for (int mt = 0; mt < 2; mt++) {
                int rbm = wm * 32 + mt * 16;
                af[mt][0] = __float_as_uint(Qs[(rbm + r) * SSTR + kb + cq]);
                af[mt][1] = __float_as_uint(Qs[(rbm + 8 + r) * SSTR + kb + cq]);
                af[mt][2] = __float_as_uint(Qs[(rbm + r) * SSTR + kb + 4 + cq]);
                af[mt][3] = __float_as_uint(Qs[(rbm + 8 + r) * SSTR + kb + 4 + cq]);
            }
            #pragma unroll
            for (int nt = 0; nt < 8; nt++) {
                int cbi = wn * 64 + nt * 8 + r;
                bf[nt][0] = __float_as_uint(Ks[cbi * SSTR + kb + cq]);
                bf[nt][1] = __float_as_uint(Ks[cbi * SSTR + kb + 4 + cq]);
            }
            #pragma unroll
            for (int mt = 0; mt < 2; mt++)
                #pragma unroll
                for (int nt = 0; nt < 8; nt++)
                    mma_tf32(acc[mt][nt], af[mt], bf[nt]);
        }

        const bool diagblk = (rb == cb);
        #pragma unroll
        for (int mt = 0; mt < 2; mt++) {
            int arow0 = wm * 32 + mt * 16 + r;
            #pragma unroll
            for (int nt = 0; nt < 8; nt++) {
                #pragma unroll
                for (int j = 0; j < 2; j++) {
                    int bcol = wn * 64 + nt * 8 + cq * 2 + j;
                    float e0 = __expf(acc[mt][nt][j] * S);
                    float e1 = __expf(acc[mt][nt][2 + j] * S);
                    partial[nt][j] += e0 + e1;
                    if (diagblk) {
                        if (arow0 == bcol)     diagE[(size_t)p * LL + bn + bcol] = e0;
                        if (arow0 + 8 == bcol) diagE[(size_t)p * LL + bn + bcol] = e1;
                    }
                }
            }
        }
    }

    #pragma unroll
    for (int nt = 0; nt < 8; nt++)
        #pragma unroll
        for (int j = 0; j < 2; j++) {
            float v = partial[nt][j];
            v += __shfl_xor_sync(0xFFFFFFFF, v, 4);
            v += __shfl_xor_sync(0xFFFFFFFF, v, 8);
            v += __shfl_xor_sync(0xFFFFFFFF, v, 16);
            partial[nt][j] = v;
        }

    __syncthreads();
    if (t < 128) csum[t] = 0.f;
    __syncthreads();
    if (r == 0) {
        #pragma unroll
        for (int nt = 0; nt < 8; nt++)
            #pragma unroll
            for (int j = 0; j < 2; j++)
                atomicAdd(&csum[wn * 64 + nt * 8 + cq * 2 + j], partial[nt][j]);
    }
    __syncthreads();
    if (t < 128)
        partG[((size_t)rbg * NPAIR + p) * LL + bn + t] = csum[t];
}

// ---------------------------------------------------------------------------
// diag[p][c] = diagE[p][c] / sum_rbg part[rbg][p][c]
// ---------------------------------------------------------------------------
__global__ __launch_bounds__(256) void divide_kernel(
    const float* __restrict__ diagE, const float* __restrict__ part,
    float* __restrict__ diag)
{
    int i = blockIdx.x * 256 + threadIdx.x;
    if (i >= NPAIR * LL) return;
    float s = 0.f;
    #pragma unroll
    for (int rb = 0; rb < RBG; rb++)
        s += part[(size_t)rb * NPAIR * LL + i];
    diag[i] = diagE[i] / s;
}

// ---------------------------------------------------------------------------
// Apply diag to V in place, tf32-rounded: V[l,e] = round(diag * V[l,e]).
// ---------------------------------------------------------------------------
__global__ __launch_bounds__(256) void apply_diag_kernel(
    float* __restrict__ V, const float* __restrict__ diag)
{
    size_t i = (size_t)blockIdx.x * 256 + threadIdx.x;    // float4 index
    const size_t total4 = (size_t)NB * LL * HID / 4;
    if (i >= total4) return;
    size_t elem = i * 4;
    int e = (int)(elem & (HID - 1));
    int l = (int)((elem >> 10) & (LL - 1));
    int n = (int)(elem >> 21);
    int h = l >> 7;
    int a = ((l & 127) << 4) | (e >> 6);
    float dd = diag[((size_t)(n * HEADS + h)) * LL + a];
    float4 v = reinterpret_cast<float4*>(V)[i];
    v.x *= dd; v.y *= dd; v.z *= dd; v.w *= dd;
    reinterpret_cast<float4*>(V)[i] = tf4(v);
}

// ---------------------------------------------------------------------------
extern "C" void kernel_launch(void* const* d_in, const int* in_sizes, int n_in,
                              void* d_out, int out_size)
{
    const float* X  = (const float*)d_in[0];
    const float* Wq = (const float*)d_in[1];
    const float* bq = (const float*)d_in[2];
    const float* Wk = (const float*)d_in[3];
    const float* bk = (const float*)d_in[4];
    const float* Wv = (const float*)d_in[5];
    const float* bv = (const float*)d_in[6];
    const float* Wo = (const float*)d_in[7];
    const float* bo = (const float*)d_in[8];
    float* out = (float*)d_out;

    float *Q, *K, *V, *Xr, *Wqr, *Wkr, *Wvr, *Wor, *dgE, *pt, *dg;
    cudaGetSymbolAddress((void**)&Q,   g_Q);
    cudaGetSymbolAddress((void**)&K,   g_K);
    cudaGetSymbolAddress((void**)&V,   g_V);
    cudaGetSymbolAddress((void**)&Xr,  g_Xr);
    cudaGetSymbolAddress((void**)&Wqr, g_Wqr);
    cudaGetSymbolAddress((void**)&Wkr, g_Wkr);
    cudaGetSymbolAddress((void**)&Wvr, g_Wvr);
    cudaGetSymbolAddress((void**)&Wor, g_Wor);
    cudaGetSymbolAddress((void**)&dgE, g_diagE);
    cudaGetSymbolAddress((void**)&pt,  g_part);
    cudaGetSymbolAddress((void**)&dg,  g_diag);

    const int score_smem = (2 * 128 * SSTR + 128) * sizeof(float);
    static int attr_done = 0;
    if (!attr_done) {
        cudaFuncSetAttribute(score_diag_tc,
                             cudaFuncAttributeMaxDynamicSharedMemorySize, score_smem);
        cudaFuncSetAttribute(gemm_qkv,
                             cudaFuncAttributeMaxDynamicSharedMemorySize, GEMM_SMEM);
        cudaFuncSetAttribute(gemm_o,
                             cudaFuncAttributeMaxDynamicSharedMemorySize, GEMM_SMEM);
        attr_done = 1;
    }

    // Pre-round inputs to tf32
    const int xn4 = MROWS * EE / 4;        // 2097152
    const int wn4 = EE * HID / 4;          // 262144
    round_copy<<<(xn4 + 255) / 256, 256>>>(X,  Xr,  xn4);
    round_copy<<<(wn4 + 255) / 256, 256>>>(Wq, Wqr, wn4);
    round_copy<<<(wn4 + 255) / 256, 256>>>(Wk, Wkr, wn4);
    round_copy<<<(wn4 + 255) / 256, 256>>>(Wv, Wvr, wn4);
    round_copy<<<(wn4 + 255) / 256, 256>>>(Wo, Wor, wn4);

    dim3 qkv_grid(HID / GBN, MROWS / GBM, 3);   // (8, 64, 3)
    gemm_qkv<<<qkv_grid, 256, GEMM_SMEM>>>(Xr, Wqr, Wkr, Wvr, bq, bk, bv, Q, K, V);

    dim3 sgrid(LL / 128, RBG, NPAIR);           // (16, 4, 64)
    score_diag_tc<<<sgrid, 256, score_smem>>>(Q, K, dgE, pt);

    divide_kernel<<<(NPAIR * LL + 255) / 256, 256>>>(dgE, pt, dg);

    const size_t total4 = (size_t)NB * LL * HID / 4;
    apply_diag_kernel<<<(unsigned)((total4 + 255) / 256), 256>>>(V, dg);

    dim3 ogrid(HID / GBN, MROWS / GBM);         // (8, 64)
    gemm_o<<<ogrid, 256, GEMM_SMEM>>>(V, Wor, bo, out);
}

// round 16
// speedup vs baseline: 1.1726x; 1.0235x over previous
#include <cuda_runtime.h>
#include <cstdint>

// Problem constants
#define NB    4
#define LL    2048
#define EE    1024
#define HID   1024
#define HEADS 16
#define DH    64
#define MROWS 8192
#define NPAIR 64
#define RBG   4
#define RPG   4

// Scratch (static device globals)
__device__ float g_Q[MROWS * HID];
__device__ float g_K[MROWS * HID];
__device__ float g_V[MROWS * HID];
__device__ float g_Xr[MROWS * EE];      // tf32-rounded X
__device__ float g_Wqr[EE * HID];
__device__ float g_Wkr[EE * HID];
__device__ float g_Wvr[EE * HID];
__device__ float g_Wor[HID * HID];
__device__ float g_diagE[NPAIR * LL];
__device__ float g_part[RBG * NPAIR * LL];
__device__ float g_diag[NPAIR * LL];

// ---------------------------------------------------------------------------
__device__ __forceinline__ uint32_t f2tf32(float x) {
    uint32_t r;
    asm("cvt.rna.tf32.f32 %0, %1;" : "=r"(r) : "f"(x));
    return r;
}

__device__ __forceinline__ float rtf(float x) {
    return __uint_as_float(f2tf32(x));
}

__device__ __forceinline__ void mma_tf32(float c[4], const uint32_t a[4], const uint32_t b[2]) {
    asm volatile(
        "mma.sync.aligned.m16n8k8.row.col.f32.tf32.tf32.f32 "
        "{%0,%1,%2,%3}, {%4,%5,%6,%7}, {%8,%9}, {%0,%1,%2,%3};\n"
        : "+f"(c[0]), "+f"(c[1]), "+f"(c[2]), "+f"(c[3])
        : "r"(a[0]), "r"(a[1]), "r"(a[2]), "r"(a[3]), "r"(b[0]), "r"(b[1]));
}

__device__ __forceinline__ float4 tf4(float4 v) {
    float4 w;
    w.x = rtf(v.x); w.y = rtf(v.y); w.z = rtf(v.z); w.w = rtf(v.w);
    return w;
}

__device__ __forceinline__ uint32_t smem_u32(const void* p) {
    return (uint32_t)__cvta_generic_to_shared(p);
}

#define CP16(dst_u32, src_ptr) \
    asm volatile("cp.async.cg.shared.global [%0], [%1], 16;\n" \
                 :: "r"(dst_u32), "l"(src_ptr) : "memory")
#define CP_COMMIT()  asm volatile("cp.async.commit_group;\n" ::: "memory")
#define CP_WAIT(n)   asm volatile("cp.async.wait_group %0;\n" :: "n"(n) : "memory")

// ---------------------------------------------------------------------------
// Fused pre-round: one launch covers X + 4 weight matrices.
// ---------------------------------------------------------------------------
#define XN4 (MROWS * EE / 4)     // 2097152
#define WN4 (EE * HID / 4)       // 262144 = 2^18
#define ALLN4 (XN4 + 4 * WN4)    // 3145728

__global__ __launch_bounds__(256) void round_all(
    const float* __restrict__ X,
    const float* __restrict__ Wq, const float* __restrict__ Wk,
    const float* __restrict__ Wv, const float* __restrict__ Wo,
    float* __restrict__ Xr,
    float* __restrict__ Wqr, float* __restrict__ Wkr,
    float* __restrict__ Wvr, float* __restrict__ Wor)
{
    int i = blockIdx.x * 256 + threadIdx.x;
    if (i >= ALLN4) return;
    const float* src; float* dst; int off;
    if (i < XN4) {
        src = X; dst = Xr; off = i;
    } else {
        int j = i - XN4;
        int w = j >> 18;                 // / WN4
        off   = j & (WN4 - 1);
        src = (w == 0) ? Wq : (w == 1) ? Wk : (w == 2) ? Wv : Wo;
        dst = (w == 0) ? Wqr : (w == 1) ? Wkr : (w == 2) ? Wvr : Wor;
    }
    reinterpret_cast<float4*>(dst)[off] =
        tf4(reinterpret_cast<const float4*>(src)[off]);
}

// ---------------------------------------------------------------------------
// cp.async GEMM: C = A @ B + bias, A/B already tf32-rounded fp32 in gmem.
// Block 128x128, BK=32, 8 warps (4m x 2n), warp tile 32x64.
// 3-stage cp.async ring, ONE __syncthreads per k-tile.
// ---------------------------------------------------------------------------
#define GBM 128
#define GBN 128
#define GBK 32
#define ASTR 36
#define BSTR 136
#define ASZ (GBM * ASTR)        // 4608 floats
#define BSZ (GBK * BSTR)        // 4352 floats
#define STG_F (ASZ + BSZ)       // 8960 floats per stage
#define GEMM_SMEM (3 * STG_F * (int)sizeof(float))   // 107520 B

__device__ __forceinline__ void stage_cp(
    const float* __restrict__ A, const float* __restrict__ B,
    int N, int K, int bm, int bn, int k0, float* As, float* Bs, int t)
{
    #pragma unroll
    for (int i = 0; i < 4; i++) {
        int idx = t + i * 256;
        int row = idx >> 3, kq = idx & 7;
        CP16(smem_u32(&As[row * ASTR + kq * 4]),
             &A[(size_t)(bm + row) * K + k0 + kq * 4]);
    }
    #pragma unroll
    for (int i = 0; i < 4; i++) {
        int idx = t + i * 256;
        int kr = idx >> 5, nq = idx & 31;
        CP16(smem_u32(&Bs[kr * BSTR + nq * 4]),
             &B[(size_t)(k0 + kr) * N + bn + nq * 4]);
    }
    CP_COMMIT();
}

__device__ __forceinline__ void gemm_body_cp(
    const float* __restrict__ A, const float* __restrict__ B,
    const float* __restrict__ bias, float* __restrict__ C,
    int N, int K, int bm, int bn, float* sm, bool round_out)
{
    const int t    = threadIdx.x;
    const int lane = t & 31, wid = t >> 5;
    const int wm = wid & 3, wn = wid >> 2;
    const int r = lane >> 2, cq = lane & 3;

    float acc[2][8][4];
    #pragma unroll
    for (int mt = 0; mt < 2; mt++)
        #pragma unroll
        for (int nt = 0; nt < 8; nt++)
            #pragma unroll
            for (int j = 0; j < 4; j++) acc[mt][nt][j] = 0.f;

    const int KT = K / GBK;     // 32

    stage_cp(A, B, N, K, bm, bn, 0, sm, sm + ASZ, t);
    stage_cp(A, B, N, K, bm, bn, GBK, sm + STG_F, sm + STG_F + ASZ, t);

    for (int kt = 0; kt < KT; kt++) {
        if (kt < KT - 2) { CP_WAIT(1); } else { CP_WAIT(0); }
        __syncthreads();

        if (kt + 2 < KT) {
            int s = (kt + 2) % 3;
            stage_cp(A, B, N, K, bm, bn, (kt + 2) * GBK,
                     sm + s * STG_F, sm + s * STG_F + ASZ, t);
        }

        const int cs = kt % 3;
        const float* Asb = sm + cs * STG_F;
        const float* Bsb = sm + cs * STG_F + ASZ;

        #pragma unroll
        for (int kk = 0; kk < 4; kk++) {
            const int kb = kk * 8;
            uint32_t af[2][4], bf[8][2];
            #pragma unroll
            for (int mt = 0; mt < 2; mt++) {
                int rb = wm * 32 + mt * 16;
                af[mt][0] = __float_as_uint(Asb[(rb + r) * ASTR + kb + cq]);
                af[mt][1] = __float_as_uint(Asb[(rb + 8 + r) * ASTR + kb + cq]);
                af[mt][2] = __float_as_uint(Asb[(rb + r) * ASTR + kb + 4 + cq]);
                af[mt][3] = __float_as_uint(Asb[(rb + 8 + r) * ASTR + kb + 4 + cq]);
            }
            #pragma unroll
            for (int nt = 0; nt < 8; nt++) {
                int cb = wn * 64 + nt * 8 + r;
                bf[nt][0] = __float_as_uint(Bsb[(kb + cq) * BSTR + cb]);
                bf[nt][1] = __float_as_uint(Bsb[(kb + 4 + cq) * BSTR + cb]);
            }
            #pragma unroll
            for (int mt = 0; mt < 2; mt++)
                #pragma unroll
                for (int nt = 0; nt < 8; nt++)
                    mma_tf32(acc[mt][nt], af[mt], bf[nt]);
        }
    }

    // Epilogue with bias; optionally tf32-round the stored values
    #pragma unroll
    for (int mt = 0; mt < 2; mt++) {
        int row0 = bm + wm * 32 + mt * 16 + r;
        #pragma unroll
        for (int nt = 0; nt < 8; nt++) {
            int col = bn + wn * 64 + nt * 8 + cq * 2;
            float b0 = bias[col], b1 = bias[col + 1];
            float2 v0 = make_float2(acc[mt][nt][0] + b0, acc[mt][nt][1] + b1);
            float2 v1 = make_float2(acc[mt][nt][2] + b0, acc[mt][nt][3] + b1);
            if (round_out) {
                v0.x = rtf(v0.x); v0.y = rtf(v0.y);
                v1.x = rtf(v1.x); v1.y = rtf(v1.y);
            }
            *reinterpret_cast<float2*>(&C[(size_t)row0 * N + col]) = v0;
            *reinterpret_cast<float2*>(&C[(size_t)(row0 + 8) * N + col]) = v1;
        }
    }
}

__global__ __launch_bounds__(256, 2) void gemm_qkv(
    const float* __restrict__ X,
    const float* __restrict__ Wq, const float* __restrict__ Wk, const float* __restrict__ Wv,
    const float* __restrict__ bq, const float* __restrict__ bk, const float* __restrict__ bv,
    float* __restrict__ Q, float* __restrict__ K, float* __restrict__ V)
{
    extern __shared__ float sm[];
    const int z = blockIdx.z;
    const float* B    = (z == 0) ? Wq : (z == 1) ? Wk : Wv;
    const float* bias = (z == 0) ? bq : (z == 1) ? bk : bv;
    float*       C    = (z == 0) ? Q  : (z == 1) ? K  : V;
    gemm_body_cp(X, B, bias, C, HID, EE,
                 blockIdx.y * GBM, blockIdx.x * GBN, sm, true);
}

__global__ __launch_bounds__(256, 2) void gemm_o(
    const float* __restrict__ V, const float* __restrict__ Wo,
    const float* __restrict__ bo, float* __restrict__ C)
{
    extern __shared__ float sm[];
    gemm_body_cp(V, Wo, bo, C, HID, HID,
                 blockIdx.y * GBM, blockIdx.x * GBN, sm, false);
}

// ---------------------------------------------------------------------------
// Score kernel with cp.async + double-buffered Q streaming.
// Block (cb, rbg, p): K[cb] tile resident; 4 Q row-blocks streamed.
// Group 0 = K + Q0; each loop iteration: wait, sync, prefetch Q(it+1) into
// the other buffer, compute on Q(it). Inputs pre-rounded tf32.
// ---------------------------------------------------------------------------
#define SSTR 68
#define SK_F (128 * SSTR)                          // 8704 floats
#define SCORE_SMEM ((3 * SK_F + 128) * (int)sizeof(float))   // 104960 B

__device__ __forceinline__ void stage_tile_cp(
    const float* __restrict__ src, float* dst, int t)
{
    // 128 rows x 64 floats, contiguous per row (DH=64), 8 x 16B per thread
    #pragma unroll
    for (int i = 0; i < 8; i++) {
        int idx = t + i * 256;
        int row = idx >> 4, q = idx & 15;
        CP16(smem_u32(&dst[row * SSTR + q * 4]),
             &src[(size_t)row * DH + q * 4]);
    }
}

__global__ __launch_bounds__(256, 2) void score_diag_tc(
    const float* __restrict__ Q, const float* __restrict__ Km,
    float* __restrict__ diagE, float* __restrict__ partG)
{
    extern __shared__ float sm[];
    float* Ks   = sm;                    // 128 x SSTR
    float* Qb0  = sm + SK_F;             // Q double buffer 0
    float* Qb1  = sm + 2 * SK_F;         // Q double buffer 1
    float* csum = sm + 3 * SK_F;         // 128

    const int t    = threadIdx.x;
    const int lane = t & 31, wid = t >> 5;
    const int wm = wid & 3, wn = wid >> 2;
    const int r = lane >> 2, cq = lane & 3;

    const int cb  = blockIdx.x;
    const int rbg = blockIdx.y;
    const int p   = blockIdx.z;
    const int bn  = cb * 128;
    const float* Qh = Q  + (size_t)p * LL * DH;
    const float* Kh = Km + (size_t)p * LL * DH;

    // Group 0: K tile + first Q tile
    stage_tile_cp(Kh + (size_t)bn * DH, Ks, t);
    stage_tile_cp(Qh + (size_t)(rbg * RPG) * 128 * DH, Qb0, t);
    CP_COMMIT();

    const float S = 1.0f / 1024.0f;
    float partial[8][2];
    #pragma unroll
    for (int nt = 0; nt < 8; nt++) { partial[nt][0] = 0.f; partial[nt][1] = 0.f; }

    for (int it = 0; it < RPG; it++) {
        const int rb = rbg * RPG + it;

        CP_WAIT(0);                      // Q(it) (and K) landed
        __syncthreads();                 // all warps done with prior compute

        if (it + 1 < RPG) {
            float* nbuf = ((it + 1) & 1) ? Qb1 : Qb0;
            stage_tile_cp(Qh + (size_t)(rb + 1) * 128 * DH, nbuf, t);
            CP_COMMIT();
        }

        const float* Qs = (it & 1) ? Qb1 : Qb0;

        float acc[2][8][4];
        #pragma unroll
        for (int mt = 0; mt < 2; mt++)
            #pragma unroll
            for (int nt = 0; nt < 8; nt++)
                #pragma unroll
                for (int j = 0; j < 4; j++) acc[mt][nt][j] = 0.f;

        #pragma unroll
        for (int kk = 0; kk < 8; kk++) {
            const int kb = kk * 8;
            uint32_t af[2][4], bf[8][2];
            #pragma unroll
            for (int mt = 0; mt < 2; mt++) {
                int rbm = wm * 32 + mt * 16;
                af[mt][0] = __float_as_uint(Qs[(rbm + r) * SSTR + kb + cq]);
                af[mt][1] = __float_as_uint(Qs[(rbm + 8 + r) * SSTR + kb + cq]);
                af[mt][2] = __float_as_uint(Qs[(rbm + r) * SSTR + kb + 4 + cq]);
                af[mt][3] = __float_as_uint(Qs[(rbm + 8 + r) * SSTR + kb + 4 + cq]);
            }
            #pragma unroll
            for (int nt = 0; nt < 8; nt++) {
                int cbi = wn * 64 + nt * 8 + r;
                bf[nt][0] = __float_as_uint(Ks[cbi * SSTR + kb + cq]);
                bf[nt][1] = __float_as_uint(Ks[cbi * SSTR + kb + 4 + cq]);
            }
            #pragma unroll
            for (int mt = 0; mt < 2; mt++)
                #pragma unroll
                for (int nt = 0; nt < 8; nt++)
                    mma_tf32(acc[mt][nt], af[mt], bf[nt]);
        }

        const bool diagblk = (rb == cb);
        #pragma unroll
        for (int mt = 0; mt < 2; mt++) {
            int arow0 = wm * 32 + mt * 16 + r;
            #pragma unroll
            for (int nt = 0; nt < 8; nt++) {
                #pragma unroll
                for (int j = 0; j < 2; j++) {
                    int bcol = wn * 64 + nt * 8 + cq * 2 + j;
                    float e0 = __expf(acc[mt][nt][j] * S);
                    float e1 = __expf(acc[mt][nt][2 + j] * S);
                    partial[nt][j] += e0 + e1;
                    if (diagblk) {
                        if (arow0 == bcol)     diagE[(size_t)p * LL + bn + bcol] = e0;
                        if (arow0 + 8 == bcol) diagE[(size_t)p * LL + bn + bcol] = e1;
                    }
                }
            }
        }
    }

    #pragma unroll
    for (int nt = 0; nt < 8; nt++)
        #pragma unroll
        for (int j = 0; j < 2; j++) {
            float v = partial[nt][j];
            v += __shfl_xor_sync(0xFFFFFFFF, v, 4);
            v += __shfl_xor_sync(0xFFFFFFFF, v, 8);
            v += __shfl_xor_sync(0xFFFFFFFF, v, 16);
            partial[nt][j] = v;
        }

    __syncthreads();
    if (t < 128) csum[t] = 0.f;
    __syncthreads();
    if (r == 0) {
        #pragma unroll
        for (int nt = 0; nt < 8; nt++)
            #pragma unroll
            for (int j = 0; j < 2; j++)
                atomicAdd(&csum[wn * 64 + nt * 8 + cq * 2 + j], partial[nt][j]);
    }
    __syncthreads();
    if (t < 128)
        partG[((size_t)rbg * NPAIR + p) * LL + bn + t] = csum[t];
}

// ---------------------------------------------------------------------------
__global__ __launch_bounds__(256) void divide_kernel(
    const float* __restrict__ diagE, const float* __restrict__ part,
    float* __restrict__ diag)
{
    int i = blockIdx.x * 256 + threadIdx.x;
    if (i >= NPAIR * LL) return;
    float s = 0.f;
    #pragma unroll
    for (int rb = 0; rb < RBG; rb++)
        s += part[(size_t)rb * NPAIR * LL + i];
    diag[i] = diagE[i] / s;
}

// ---------------------------------------------------------------------------
__global__ __launch_bounds__(256) void apply_diag_kernel(
    float* __restrict__ V, const float* __restrict__ diag)
{
    size_t i = (size_t)blockIdx.x * 256 + threadIdx.x;    // float4 index
    const size_t total4 = (size_t)NB * LL * HID / 4;
    if (i >= total4) return;
    size_t elem = i * 4;
    int e = (int)(elem & (HID - 1));
    int l = (int)((elem >> 10) & (LL - 1));
    int n = (int)(elem >> 21);
    int h = l >> 7;
    int a = ((l & 127) << 4) | (e >> 6);
    float dd = diag[((size_t)(n * HEADS + h)) * LL + a];
    float4 v = reinterpret_cast<float4*>(V)[i];
    v.x *= dd; v.y *= dd; v.z *= dd; v.w *= dd;
    reinterpret_cast<float4*>(V)[i] = tf4(v);
}

// ---------------------------------------------------------------------------
extern "C" void kernel_launch(void* const* d_in, const int* in_sizes, int n_in,
                              void* d_out, int out_size)
{
    const float* X  = (const float*)d_in[0];
    const float* Wq = (const float*)d_in[1];
    const float* bq = (const float*)d_in[2];
    const float* Wk = (const float*)d_in[3];
    const float* bk = (const float*)d_in[4];
    const float* Wv = (const float*)d_in[5];
    const float* bv = (const float*)d_in[6];
    const float* Wo = (const float*)d_in[7];
    const float* bo = (const float*)d_in[8];
    float* out = (float*)d_out;

    float *Q, *K, *V, *Xr, *Wqr, *Wkr, *Wvr, *Wor, *dgE, *pt, *dg;
    cudaGetSymbolAddress((void**)&Q,   g_Q);
    cudaGetSymbolAddress((void**)&K,   g_K);
    cudaGetSymbolAddress((void**)&V,   g_V);
    cudaGetSymbolAddress((void**)&Xr,  g_Xr);
    cudaGetSymbolAddress((void**)&Wqr, g_Wqr);
    cudaGetSymbolAddress((void**)&Wkr, g_Wkr);
    cudaGetSymbolAddress((void**)&Wvr, g_Wvr);
    cudaGetSymbolAddress((void**)&Wor, g_Wor);
    cudaGetSymbolAddress((void**)&dgE, g_diagE);
    cudaGetSymbolAddress((void**)&pt,  g_part);
    cudaGetSymbolAddress((void**)&dg,  g_diag);

    static int attr_done = 0;
    if (!attr_done) {
        cudaFuncSetAttribute(score_diag_tc,
                             cudaFuncAttributeMaxDynamicSharedMemorySize, SCORE_SMEM);
        cudaFuncSetAttribute(gemm_qkv,
                             cudaFuncAttributeMaxDynamicSharedMemorySize, GEMM_SMEM);
        cudaFuncSetAttribute(gemm_o,
                             cudaFuncAttributeMaxDynamicSharedMemorySize, GEMM_SMEM);
        attr_done = 1;
    }

    round_all<<<(ALLN4 + 255) / 256, 256>>>(X, Wq, Wk, Wv, Wo,
                                            Xr, Wqr, Wkr, Wvr, Wor);

    dim3 qkv_grid(HID / GBN, MROWS / GBM, 3);   // (8, 64, 3)
    gemm_qkv<<<qkv_grid, 256, GEMM_SMEM>>>(Xr, Wqr, Wkr, Wvr, bq, bk, bv, Q, K, V);

    dim3 sgrid(LL / 128, RBG, NPAIR);           // (16, 4, 64)
    score_diag_tc<<<sgrid, 256, SCORE_SMEM>>>(Q, K, dgE, pt);

    divide_kernel<<<(NPAIR * LL + 255) / 256, 256>>>(dgE, pt, dg);

    const size_t total4 = (size_t)NB * LL * HID / 4;
    apply_diag_kernel<<<(unsigned)((total4 + 255) / 256), 256>>>(V, dg);

    dim3 ogrid(HID / GBN, MROWS / GBM);         // (8, 64)
    gemm_o<<<ogrid, 256, GEMM_SMEM>>>(V, Wor, bo, out);
}

// round 17
// speedup vs baseline: 1.2092x; 1.0312x over previous
#include <cuda_runtime.h>
#include <cstdint>

// Problem constants
#define NB    4
#define LL    2048
#define EE    1024
#define HID   1024
#define HEADS 16
#define DH    64
#define MROWS 8192
#define NPAIR 64
#define RBG   4
#define RPG   4

// Scratch (static device globals)
__device__ float g_Q[MROWS * HID];
__device__ float g_K[MROWS * HID];
__device__ float g_V[MROWS * HID];
__device__ float g_Xr[MROWS * EE];      // tf32-rounded X
__device__ float g_Wqr[EE * HID];
__device__ float g_Wkr[EE * HID];
__device__ float g_Wvr[EE * HID];
__device__ float g_Wor[HID * HID];
__device__ float g_diagE[NPAIR * LL];
__device__ float g_part[RBG * NPAIR * LL];
__device__ float g_diag[NPAIR * LL];

// ---------------------------------------------------------------------------
__device__ __forceinline__ uint32_t f2tf32(float x) {
    uint32_t r;
    asm("cvt.rna.tf32.f32 %0, %1;" : "=r"(r) : "f"(x));
    return r;
}

__device__ __forceinline__ float rtf(float x) {
    return __uint_as_float(f2tf32(x));
}

__device__ __forceinline__ void mma_tf32(float c[4], const uint32_t a[4], const uint32_t b[2]) {
    asm volatile(
        "mma.sync.aligned.m16n8k8.row.col.f32.tf32.tf32.f32 "
        "{%0,%1,%2,%3}, {%4,%5,%6,%7}, {%8,%9}, {%0,%1,%2,%3};\n"
        : "+f"(c[0]), "+f"(c[1]), "+f"(c[2]), "+f"(c[3])
        : "r"(a[0]), "r"(a[1]), "r"(a[2]), "r"(a[3]), "r"(b[0]), "r"(b[1]));
}

__device__ __forceinline__ float4 tf4(float4 v) {
    float4 w;
    w.x = rtf(v.x); w.y = rtf(v.y); w.z = rtf(v.z); w.w = rtf(v.w);
    return w;
}

__device__ __forceinline__ uint32_t smem_u32(const void* p) {
    return (uint32_t)__cvta_generic_to_shared(p);
}

#define CP16(dst_u32, src_ptr) \
    asm volatile("cp.async.cg.shared.global [%0], [%1], 16;\n" \
                 :: "r"(dst_u32), "l"(src_ptr) : "memory")
#define CP_COMMIT()  asm volatile("cp.async.commit_group;\n" ::: "memory")
#define CP_WAIT(n)   asm volatile("cp.async.wait_group %0;\n" :: "n"(n) : "memory")

// ---------------------------------------------------------------------------
// Fused pre-round: one launch covers X + 4 weight matrices.
// ---------------------------------------------------------------------------
#define XN4 (MROWS * EE / 4)     // 2097152
#define WN4 (EE * HID / 4)       // 262144 = 2^18
#define ALLN4 (XN4 + 4 * WN4)    // 3145728

__global__ __launch_bounds__(256) void round_all(
    const float* __restrict__ X,
    const float* __restrict__ Wq, const float* __restrict__ Wk,
    const float* __restrict__ Wv, const float* __restrict__ Wo,
    float* __restrict__ Xr,
    float* __restrict__ Wqr, float* __restrict__ Wkr,
    float* __restrict__ Wvr, float* __restrict__ Wor)
{
    int i = blockIdx.x * 256 + threadIdx.x;
    if (i >= ALLN4) return;
    const float* src; float* dst; int off;
    if (i < XN4) {
        src = X; dst = Xr; off = i;
    } else {
        int j = i - XN4;
        int w = j >> 18;                 // / WN4
        off   = j & (WN4 - 1);
        src = (w == 0) ? Wq : (w == 1) ? Wk : (w == 2) ? Wv : Wo;
        dst = (w == 0) ? Wqr : (w == 1) ? Wkr : (w == 2) ? Wvr : Wor;
    }
    reinterpret_cast<float4*>(dst)[off] =
        tf4(reinterpret_cast<const float4*>(src)[off]);
}

// ---------------------------------------------------------------------------
// cp.async GEMM: C = A @ B + bias, A/B already tf32-rounded fp32 in gmem.
// Block 128x128, BK=32, 4 warps (2m x 2n), warp tile 64x64, 128 threads.
// 3-stage cp.async ring, ONE __syncthreads per k-tile.
// Per warp-kk: 16 A-LDS + 16 B-LDS feed 32 mma (1.0 LDS/mma).
// ---------------------------------------------------------------------------
#define GBM 128
#define GBN 128
#define GBK 32
#define GTHREADS 128
#define ASTR 36
#define BSTR 136
#define ASZ (GBM * ASTR)        // 4608 floats
#define BSZ (GBK * BSTR)        // 4352 floats
#define STG_F (ASZ + BSZ)       // 8960 floats per stage
#define GEMM_SMEM (3 * STG_F * (int)sizeof(float))   // 107520 B

__device__ __forceinline__ void stage_cp(
    const float* __restrict__ A, const float* __restrict__ B,
    int N, int K, int bm, int bn, int k0, float* As, float* Bs, int t)
{
    #pragma unroll
    for (int i = 0; i < 8; i++) {
        int idx = t + i * GTHREADS;
        int row = idx >> 3, kq = idx & 7;
        CP16(smem_u32(&As[row * ASTR + kq * 4]),
             &A[(size_t)(bm + row) * K + k0 + kq * 4]);
    }
    #pragma unroll
    for (int i = 0; i < 8; i++) {
        int idx = t + i * GTHREADS;
        int kr = idx >> 5, nq = idx & 31;
        CP16(smem_u32(&Bs[kr * BSTR + nq * 4]),
             &B[(size_t)(k0 + kr) * N + bn + nq * 4]);
    }
    CP_COMMIT();
}

__device__ __forceinline__ void gemm_body_cp(
    const float* __restrict__ A, const float* __restrict__ B,
    const float* __restrict__ bias, float* __restrict__ C,
    int N, int K, int bm, int bn, float* sm, bool round_out)
{
    const int t    = threadIdx.x;
    const int lane = t & 31, wid = t >> 5;     // 4 warps
    const int wm = wid & 1, wn = wid >> 1;     // 2m x 2n
    const int r = lane >> 2, cq = lane & 3;

    float acc[4][8][4];
    #pragma unroll
    for (int mt = 0; mt < 4; mt++)
        #pragma unroll
        for (int nt = 0; nt < 8; nt++)
            #pragma unroll
            for (int j = 0; j < 4; j++) acc[mt][nt][j] = 0.f;

    const int KT = K / GBK;     // 32

    stage_cp(A, B, N, K, bm, bn, 0, sm, sm + ASZ, t);
    stage_cp(A, B, N, K, bm, bn, GBK, sm + STG_F, sm + STG_F + ASZ, t);

    for (int kt = 0; kt < KT; kt++) {
        if (kt < KT - 2) { CP_WAIT(1); } else { CP_WAIT(0); }
        __syncthreads();

        if (kt + 2 < KT) {
            int s = (kt + 2) % 3;
            stage_cp(A, B, N, K, bm, bn, (kt + 2) * GBK,
                     sm + s * STG_F, sm + s * STG_F + ASZ, t);
        }

        const int cs = kt % 3;
        const float* Asb = sm + cs * STG_F;
        const float* Bsb = sm + cs * STG_F + ASZ;

        #pragma unroll
        for (int kk = 0; kk < 4; kk++) {
            const int kb = kk * 8;
            uint32_t af[4][4], bf[8][2];
            #pragma unroll
            for (int mt = 0; mt < 4; mt++) {
                int rb = wm * 64 + mt * 16;
                af[mt][0] = __float_as_uint(Asb[(rb + r) * ASTR + kb + cq]);
                af[mt][1] = __float_as_uint(Asb[(rb + 8 + r) * ASTR + kb + cq]);
                af[mt][2] = __float_as_uint(Asb[(rb + r) * ASTR + kb + 4 + cq]);
                af[mt][3] = __float_as_uint(Asb[(rb + 8 + r) * ASTR + kb + 4 + cq]);
            }
            #pragma unroll
            for (int nt = 0; nt < 8; nt++) {
                int cb = wn * 64 + nt * 8 + r;
                bf[nt][0] = __float_as_uint(Bsb[(kb + cq) * BSTR + cb]);
                bf[nt][1] = __float_as_uint(Bsb[(kb + 4 + cq) * BSTR + cb]);
            }
            #pragma unroll
            for (int mt = 0; mt < 4; mt++)
                #pragma unroll
                for (int nt = 0; nt < 8; nt++)
                    mma_tf32(acc[mt][nt], af[mt], bf[nt]);
        }
    }

    // Epilogue with bias; optionally tf32-round the stored values
    #pragma unroll
    for (int mt = 0; mt < 4; mt++) {
        int row0 = bm + wm * 64 + mt * 16 + r;
        #pragma unroll
        for (int nt = 0; nt < 8; nt++) {
            int col = bn + wn * 64 + nt * 8 + cq * 2;
            float b0 = bias[col], b1 = bias[col + 1];
            float2 v0 = make_float2(acc[mt][nt][0] + b0, acc[mt][nt][1] + b1);
            float2 v1 = make_float2(acc[mt][nt][2] + b0, acc[mt][nt][3] + b1);
            if (round_out) {
                v0.x = rtf(v0.x); v0.y = rtf(v0.y);
                v1.x = rtf(v1.x); v1.y = rtf(v1.y);
            }
            *reinterpret_cast<float2*>(&C[(size_t)row0 * N + col]) = v0;
            *reinterpret_cast<float2*>(&C[(size_t)(row0 + 8) * N + col]) = v1;
        }
    }
}

__global__ __launch_bounds__(GTHREADS, 2) void gemm_qkv(
    const float* __restrict__ X,
    const float* __restrict__ Wq, const float* __restrict__ Wk, const float* __restrict__ Wv,
    const float* __restrict__ bq, const float* __restrict__ bk, const float* __restrict__ bv,
    float* __restrict__ Q, float* __restrict__ K, float* __restrict__ V)
{
    extern __shared__ float sm[];
    const int z = blockIdx.z;
    const float* B    = (z == 0) ? Wq : (z == 1) ? Wk : Wv;
    const float* bias = (z == 0) ? bq : (z == 1) ? bk : bv;
    float*       C    = (z == 0) ? Q  : (z == 1) ? K  : V;
    gemm_body_cp(X, B, bias, C, HID, EE,
                 blockIdx.y * GBM, blockIdx.x * GBN, sm, true);
}

__global__ __launch_bounds__(GTHREADS, 2) void gemm_o(
    const float* __restrict__ V, const float* __restrict__ Wo,
    const float* __restrict__ bo, float* __restrict__ C)
{
    extern __shared__ float sm[];
    gemm_body_cp(V, Wo, bo, C, HID, HID,
                 blockIdx.y * GBM, blockIdx.x * GBN, sm, false);
}

// ---------------------------------------------------------------------------
// Score kernel with cp.async + double-buffered Q streaming (unchanged).
// ---------------------------------------------------------------------------
#define SSTR 68
#define SK_F (128 * SSTR)                          // 8704 floats
#define SCORE_SMEM ((3 * SK_F + 128) * (int)sizeof(float))   // 104960 B

__device__ __forceinline__ void stage_tile_cp(
    const float* __restrict__ src, float* dst, int t)
{
    #pragma unroll
    for (int i = 0; i < 8; i++) {
        int idx = t + i * 256;
        int row = idx >> 4, q = idx & 15;
        CP16(smem_u32(&dst[row * SSTR + q * 4]),
             &src[(size_t)row * DH + q * 4]);
    }
}

__global__ __launch_bounds__(256, 2) void score_diag_tc(
    const float* __restrict__ Q, const float* __restrict__ Km,
    float* __restrict__ diagE, float* __restrict__ partG)
{
    extern __shared__ float sm[];
    float* Ks   = sm;                    // 128 x SSTR
    float* Qb0  = sm + SK_F;
    float* Qb1  = sm + 2 * SK_F;
    float* csum = sm + 3 * SK_F;         // 128

    const int t    = threadIdx.x;
    const int lane = t & 31, wid = t >> 5;
    const int wm = wid & 3, wn = wid >> 2;
    const int r = lane >> 2, cq = lane & 3;

    const int cb  = blockIdx.x;
    const int rbg = blockIdx.y;
    const int p   = blockIdx.z;
    const int bn  = cb * 128;
    const float* Qh = Q  + (size_t)p * LL * DH;
    const float* Kh = Km + (size_t)p * LL * DH;

    stage_tile_cp(Kh + (size_t)bn * DH, Ks, t);
    stage_tile_cp(Qh + (size_t)(rbg * RPG) * 128 * DH, Qb0, t);
    CP_COMMIT();

    const float S = 1.0f / 1024.0f;
    float partial[8][2];
    #pragma unroll
    for (int nt = 0; nt < 8; nt++) { partial[nt][0] = 0.f; partial[nt][1] = 0.f; }

    for (int it = 0; it < RPG; it++) {
        const int rb = rbg * RPG + it;

        CP_WAIT(0);
        __syncthreads();

        if (it + 1 < RPG) {
            float* nbuf = ((it + 1) & 1) ? Qb1 : Qb0;
            stage_tile_cp(Qh + (size_t)(rb + 1) * 128 * DH, nbuf, t);
            CP_COMMIT();
        }

        const float* Qs = (it & 1) ? Qb1 : Qb0;

        float acc[2][8][4];
        #pragma unroll
        for (int mt = 0; mt < 2; mt++)
            #pragma unroll
            for (int nt = 0; nt < 8; nt++)
                #pragma unroll
                for (int j = 0; j < 4; j++) acc[mt][nt][j] = 0.f;

        #pragma unroll
        for (int kk = 0; kk < 8; kk++) {
            const int kb = kk * 8;
            uint32_t af[2][4], bf[8][2];
            #pragma unroll
            for (int mt = 0; mt < 2; mt++) {
                int rbm = wm * 32 + mt * 16;
                af[mt][0] = __float_as_uint(Qs[(rbm + r) * SSTR + kb + cq]);
                af[mt][1] = __float_as_uint(Qs[(rbm + 8 + r) * SSTR + kb + cq]);
                af[mt][2] = __float_as_uint(Qs[(rbm + r) * SSTR + kb + 4 + cq]);
                af[mt][3] = __float_as_uint(Qs[(rbm + 8 + r) * SSTR + kb + 4 + cq]);
            }
            #pragma unroll
            for (int nt = 0; nt < 8; nt++) {
                int cbi = wn * 64 + nt * 8 + r;
                bf[nt][0] = __float_as_uint(Ks[cbi * SSTR + kb + cq]);
                bf[nt][1] = __float_as_uint(Ks[cbi * SSTR + kb + 4 + cq]);
            }
            #pragma unroll
            for (int mt = 0; mt < 2; mt++)
                #pragma unroll
                for (int nt = 0; nt < 8; nt++)
                    mma_tf32(acc[mt][nt], af[mt], bf[nt]);
        }

        const bool diagblk = (rb == cb);
        #pragma unroll
        for (int mt = 0; mt < 2; mt++) {
            int arow0 = wm * 32 + mt * 16 + r;
            #pragma unroll
            for (int nt = 0; nt < 8; nt++) {
                #pragma unroll
                for (int j = 0; j < 2; j++) {
                    int bcol = wn * 64 + nt * 8 + cq * 2 + j;
                    float e0 = __expf(acc[mt][nt][j] * S);
                    float e1 = __expf(acc[mt][nt][2 + j] * S);
                    partial[nt][j] += e0 + e1;
                    if (diagblk) {
                        if (arow0 == bcol)     diagE[(size_t)p * LL + bn + bcol] = e0;
                        if (arow0 + 8 == bcol) diagE[(size_t)p * LL + bn + bcol] = e1;
                    }
                }
            }
        }
    }

    #pragma unroll
    for (int nt = 0; nt < 8; nt++)
        #pragma unroll
        for (int j = 0; j < 2; j++) {
            float v = partial[nt][j];
            v += __shfl_xor_sync(0xFFFFFFFF, v, 4);
            v += __shfl_xor_sync(0xFFFFFFFF, v, 8);
            v += __shfl_xor_sync(0xFFFFFFFF, v, 16);
            partial[nt][j] = v;
        }

    __syncthreads();
    if (t < 128) csum[t] = 0.f;
    __syncthreads();
    if (r == 0) {
        #pragma unroll
        for (int nt = 0; nt < 8; nt++)
            #pragma unroll
            for (int j = 0; j < 2; j++)
                atomicAdd(&csum[wn * 64 + nt * 8 + cq * 2 + j], partial[nt][j]);
    }
    __syncthreads();
    if (t < 128)
        partG[((size_t)rbg * NPAIR + p) * LL + bn + t] = csum[t];
}

// ---------------------------------------------------------------------------
__global__ __launch_bounds__(256) void divide_kernel(
    const float* __restrict__ diagE, const float* __restrict__ part,
    float* __restrict__ diag)
{
    int i = blockIdx.x * 256 + threadIdx.x;
    if (i >= NPAIR * LL) return;
    float s = 0.f;
    #pragma unroll
    for (int rb = 0; rb < RBG; rb++)
        s += part[(size_t)rb * NPAIR * LL + i];
    diag[i] = diagE[i] / s;
}

// ---------------------------------------------------------------------------
__global__ __launch_bounds__(256) void apply_diag_kernel(
    float* __restrict__ V, const float* __restrict__ diag)
{
    size_t i = (size_t)blockIdx.x * 256 + threadIdx.x;    // float4 index
    const size_t total4 = (size_t)NB * LL * HID / 4;
    if (i >= total4) return;
    size_t elem = i * 4;
    int e = (int)(elem & (HID - 1));
    int l = (int)((elem >> 10) & (LL - 1));
    int n = (int)(elem >> 21);
    int h = l >> 7;
    int a = ((l & 127) << 4) | (e >> 6);
    float dd = diag[((size_t)(n * HEADS + h)) * LL + a];
    float4 v = reinterpret_cast<float4*>(V)[i];
    v.x *= dd; v.y *= dd; v.z *= dd; v.w *= dd;
    reinterpret_cast<float4*>(V)[i] = tf4(v);
}

// ---------------------------------------------------------------------------
extern "C" void kernel_launch(void* const* d_in, const int* in_sizes, int n_in,
                              void* d_out, int out_size)
{
    const float* X  = (const float*)d_in[0];
    const float* Wq = (const float*)d_in[1];
    const float* bq = (const float*)d_in[2];
    const float* Wk = (const float*)d_in[3];
    const float* bk = (const float*)d_in[4];
    const float* Wv = (const float*)d_in[5];
    const float* bv = (const float*)d_in[6];
    const float* Wo = (const float*)d_in[7];
    const float* bo = (const float*)d_in[8];
    float* out = (float*)d_out;

    float *Q, *K, *V, *Xr, *Wqr, *Wkr, *Wvr, *Wor, *dgE, *pt, *dg;
    cudaGetSymbolAddress((void**)&Q,   g_Q);
    cudaGetSymbolAddress((void**)&K,   g_K);
    cudaGetSymbolAddress((void**)&V,   g_V);
    cudaGetSymbolAddress((void**)&Xr,  g_Xr);
    cudaGetSymbolAddress((void**)&Wqr, g_Wqr);
    cudaGetSymbolAddress((void**)&Wkr, g_Wkr);
    cudaGetSymbolAddress((void**)&Wvr, g_Wvr);
    cudaGetSymbolAddress((void**)&Wor, g_Wor);
    cudaGetSymbolAddress((void**)&dgE, g_diagE);
    cudaGetSymbolAddress((void**)&pt,  g_part);
    cudaGetSymbolAddress((void**)&dg,  g_diag);

    static int attr_done = 0;
    if (!attr_done) {
        cudaFuncSetAttribute(score_diag_tc,
                             cudaFuncAttributeMaxDynamicSharedMemorySize, SCORE_SMEM);
        cudaFuncSetAttribute(gemm_qkv,
                             cudaFuncAttributeMaxDynamicSharedMemorySize, GEMM_SMEM);
        cudaFuncSetAttribute(gemm_o,
                             cudaFuncAttributeMaxDynamicSharedMemorySize, GEMM_SMEM);
        attr_done = 1;
    }

    round_all<<<(ALLN4 + 255) / 256, 256>>>(X, Wq, Wk, Wv, Wo,
                                            Xr, Wqr, Wkr, Wvr, Wor);

    dim3 qkv_grid(HID / GBN, MROWS / GBM, 3);   // (8, 64, 3)
    gemm_qkv<<<qkv_grid, GTHREADS, GEMM_SMEM>>>(Xr, Wqr, Wkr, Wvr, bq, bk, bv, Q, K, V);

    dim3 sgrid(LL / 128, RBG, NPAIR);           // (16, 4, 64)
    score_diag_tc<<<sgrid, 256, SCORE_SMEM>>>(Q, K, dgE, pt);

    divide_kernel<<<(NPAIR * LL + 255) / 256, 256>>>(dgE, pt, dg);

    const size_t total4 = (size_t)NB * LL * HID / 4;
    apply_diag_kernel<<<(unsigned)((total4 + 255) / 256), 256>>>(V, dg);

    dim3 ogrid(HID / GBN, MROWS / GBM);         // (8, 64)
    gemm_o<<<ogrid, GTHREADS, GEMM_SMEM>>>(V, Wor, bo, out);
}